// round 1
// baseline (speedup 1.0000x reference)
#include <cuda_runtime.h>
#include <cstdint>

// PyramidROIAlign:
//   boxes: (2, 1000, 4) f32  [y1, x1, y2, x2] normalized
//   p2..p5: (2, S, S, 256) f32, S = 256/128/64/32, NHWC
//   out:  (2, 1000, 7, 7, 256) f32
//
// One thread handles one (b, n, py, px) pool point for 4 channels (float4).
// 64 threads cover the 256-channel vector -> fully coalesced 1KB rows.

#define BATCH   2
#define NROI    1000
#define POOLH   7
#define POOLW   7
#define NCH     256
#define NCH4    (NCH / 4)   // 64 float4 per point

__global__ __launch_bounds__(256) void pyramid_roi_align_kernel(
    const float* __restrict__ boxes,
    const float* __restrict__ p2,
    const float* __restrict__ p3,
    const float* __restrict__ p4,
    const float* __restrict__ p5,
    float* __restrict__ out)
{
    const long long total = (long long)BATCH * NROI * POOLH * POOLW * NCH4;
    long long gid = (long long)blockIdx.x * blockDim.x + threadIdx.x;
    if (gid >= total) return;

    int c4   = (int)(gid & (NCH4 - 1)) * 4;   // channel offset (multiple of 4)
    long long pt = gid >> 6;                  // point index: (b, n, py, px)
    int px = (int)(pt % POOLW);
    long long t1 = pt / POOLW;
    int py = (int)(t1 % POOLH);
    long long t2 = t1 / POOLH;
    int n  = (int)(t2 % NROI);
    int b  = (int)(t2 / NROI);

    // Load box (16B aligned: boxes + 4 floats per roi)
    const float4 bx = __ldg((const float4*)(boxes) + (b * NROI + n));
    float y1 = bx.x, x1 = bx.y, y2 = bx.z, x2 = bx.w;
    float h = y2 - y1;
    float w = x2 - x1;

    // roi_level = clip(round(log2(sqrt(max(h*w,1e-12)) / (224/1024))), 2, 5)
    // Match XLA's f32 op sequence; rintf = round-half-to-even like jnp.round.
    float lvlf = log2f(sqrtf(fmaxf(h * w, 1e-12f)) / 0.21875f);
    int level = (int)rintf(lvlf);
    level = min(max(level, 2), 5);

    const float* feat;
    int H;
    if (level == 2)      { feat = p2; H = 256; }
    else if (level == 3) { feat = p3; H = 128; }
    else if (level == 4) { feat = p4; H = 64;  }
    else                 { feat = p5; H = 32;  }
    // W == H (square pyramid levels)

    float Hm1 = (float)(H - 1);
    float ty = (float)py * (1.0f / 6.0f);
    float tx = (float)px * (1.0f / 6.0f);
    float ysf = (y1 + h * ty) * Hm1;
    float xsf = (x1 + w * tx) * Hm1;

    float y0f = floorf(ysf);
    float x0f = floorf(xsf);
    float wy = ysf - y0f;   // weights from UNCLAMPED floor (matches reference)
    float wx = xsf - x0f;

    int y0  = min(max((int)y0f, 0), H - 1);
    int y1i = min(max((int)y0f + 1, 0), H - 1);
    int x0  = min(max((int)x0f, 0), H - 1);
    int x1i = min(max((int)x0f + 1, 0), H - 1);

    // NHWC: feat[((b*H + y)*W + x)*256 + c]
    long long rowb0 = ((long long)(b * H + y0)) * H;
    long long rowb1 = ((long long)(b * H + y1i)) * H;
    const float4* f00 = (const float4*)(feat + ((rowb0 + x0 ) * NCH + c4));
    const float4* f01 = (const float4*)(feat + ((rowb0 + x1i) * NCH + c4));
    const float4* f10 = (const float4*)(feat + ((rowb1 + x0 ) * NCH + c4));
    const float4* f11 = (const float4*)(feat + ((rowb1 + x1i) * NCH + c4));

    float4 v00 = __ldg(f00);
    float4 v01 = __ldg(f01);
    float4 v10 = __ldg(f10);
    float4 v11 = __ldg(f11);

    // top = v00 + wx*(v01 - v00); bot = v10 + wx*(v11 - v10); out = top + wy*(bot - top)
    float4 r;
    {
        float t, bo;
        t  = v00.x + wx * (v01.x - v00.x);
        bo = v10.x + wx * (v11.x - v10.x);
        r.x = t + wy * (bo - t);
        t  = v00.y + wx * (v01.y - v00.y);
        bo = v10.y + wx * (v11.y - v10.y);
        r.y = t + wy * (bo - t);
        t  = v00.z + wx * (v01.z - v00.z);
        bo = v10.z + wx * (v11.z - v10.z);
        r.z = t + wy * (bo - t);
        t  = v00.w + wx * (v01.w - v00.w);
        bo = v10.w + wx * (v11.w - v10.w);
        r.w = t + wy * (bo - t);
    }

    long long oidx = ((((long long)(b * NROI + n) * POOLH + py) * POOLW + px) * NCH + c4);
    *(float4*)(out + oidx) = r;
}

extern "C" void kernel_launch(void* const* d_in, const int* in_sizes, int n_in,
                              void* d_out, int out_size)
{
    const float* boxes = (const float*)d_in[0];
    const float* p2    = (const float*)d_in[1];
    const float* p3    = (const float*)d_in[2];
    const float* p4    = (const float*)d_in[3];
    const float* p5    = (const float*)d_in[4];
    float* out = (float*)d_out;

    const long long total = (long long)BATCH * NROI * POOLH * POOLW * NCH4; // 6,272,000
    int threads = 256;
    int blocks = (int)((total + threads - 1) / threads);
    pyramid_roi_align_kernel<<<blocks, threads>>>(boxes, p2, p3, p4, p5, out);
}

// round 2
// speedup vs baseline: 1.2419x; 1.2419x over previous
#include <cuda_runtime.h>
#include <cstdint>

// PyramidROIAlign:
//   boxes: (2, 1000, 4) f32  [y1, x1, y2, x2] normalized
//   p2..p5: (2, S, S, 256) f32, S = 256/128/64/32, NHWC
//   out:  (2, 1000, 7, 7, 256) f32
//
// Block = one ROI. 49 pool points x 64 float4 channels = 3136 float4 elements.
// Per-point scalar math (level select, bilinear coords) computed ONCE by the
// first 49 threads into smem; the hot loop is pure LDG.128/FFMA/STG.128.

#define BATCH   2
#define NROI    1000
#define POOLH   7
#define POOLW   7
#define NCH     256
#define NCH4    (NCH / 4)          // 64
#define POINTS  (POOLH * POOLW)    // 49
#define ELEMS   (POINTS * NCH4)    // 3136 = 12*256 + 64

struct PtParams {
    const float4* p00;
    const float4* p01;
    const float4* p10;
    const float4* p11;
    float wx, wy;
};

__global__ __launch_bounds__(256) void pyramid_roi_align_kernel(
    const float* __restrict__ boxes,
    const float* __restrict__ p2,
    const float* __restrict__ p3,
    const float* __restrict__ p4,
    const float* __restrict__ p5,
    float4* __restrict__ out)
{
    __shared__ PtParams pts[POINTS];

    const int roi = blockIdx.x;          // 0..1999
    const int tid = threadIdx.x;
    const int b = roi >= NROI ? 1 : 0;
    const int n = roi - b * NROI;

    if (tid < POINTS) {
        const int py = tid / POOLW;
        const int px = tid - py * POOLW;

        const float4 bx = __ldg((const float4*)(boxes) + roi);
        const float y1 = bx.x, x1 = bx.y, y2 = bx.z, x2 = bx.w;
        const float h = y2 - y1;
        const float w = x2 - x1;

        // roi_level = clip(round(log2(sqrt(max(h*w,1e-12)) / (224/1024))), 2, 5)
        // rintf = round-half-to-even, matches jnp.round.
        const float lvlf = log2f(sqrtf(fmaxf(h * w, 1e-12f)) / 0.21875f);
        int level = (int)rintf(lvlf);
        level = min(max(level, 2), 5);

        const float* feat;
        int H;
        if (level == 2)      { feat = p2; H = 256; }
        else if (level == 3) { feat = p3; H = 128; }
        else if (level == 4) { feat = p4; H = 64;  }
        else                 { feat = p5; H = 32;  }

        const float Hm1 = (float)(H - 1);
        const float ty = (float)py * (1.0f / 6.0f);
        const float tx = (float)px * (1.0f / 6.0f);
        const float ysf = (y1 + h * ty) * Hm1;
        const float xsf = (x1 + w * tx) * Hm1;

        const float y0f = floorf(ysf);
        const float x0f = floorf(xsf);
        const float wy = ysf - y0f;   // weights from UNCLAMPED floor (matches ref)
        const float wx = xsf - x0f;

        const int y0  = min(max((int)y0f, 0), H - 1);
        const int y1i = min(max((int)y0f + 1, 0), H - 1);
        const int x0  = min(max((int)x0f, 0), H - 1);
        const int x1i = min(max((int)x0f + 1, 0), H - 1);

        // NHWC float4 view: feat4[((b*H + y)*H + x)*64 + c]
        const float4* f4 = (const float4*)feat;
        const int rowb0 = (b * H + y0)  * H;
        const int rowb1 = (b * H + y1i) * H;
        PtParams P;
        P.p00 = f4 + (rowb0 + x0 ) * NCH4;
        P.p01 = f4 + (rowb0 + x1i) * NCH4;
        P.p10 = f4 + (rowb1 + x0 ) * NCH4;
        P.p11 = f4 + (rowb1 + x1i) * NCH4;
        P.wx = wx;
        P.wy = wy;
        pts[tid] = P;
    }
    __syncthreads();

    float4* __restrict__ outb = out + (long long)roi * ELEMS;

    #pragma unroll
    for (int i = 0; i < 13; i++) {
        const int e = i * 256 + tid;
        if (i == 12 && tid >= 64) break;   // tail: only 64 elements left

        const int pt = e >> 6;      // pool point 0..48
        const int c  = e & 63;      // float4 channel 0..63

        const PtParams P = pts[pt]; // smem broadcast within 64-thread groups

        const float4 v00 = __ldg(P.p00 + c);
        const float4 v01 = __ldg(P.p01 + c);
        const float4 v10 = __ldg(P.p10 + c);
        const float4 v11 = __ldg(P.p11 + c);

        const float wx = P.wx, wy = P.wy;
        float4 r;
        {
            float t, bo;
            t  = v00.x + wx * (v01.x - v00.x);
            bo = v10.x + wx * (v11.x - v10.x);
            r.x = t + wy * (bo - t);
            t  = v00.y + wx * (v01.y - v00.y);
            bo = v10.y + wx * (v11.y - v10.y);
            r.y = t + wy * (bo - t);
            t  = v00.z + wx * (v01.z - v00.z);
            bo = v10.z + wx * (v11.z - v10.z);
            r.z = t + wy * (bo - t);
            t  = v00.w + wx * (v01.w - v00.w);
            bo = v10.w + wx * (v11.w - v10.w);
            r.w = t + wy * (bo - t);
        }

        outb[e] = r;
    }
}

extern "C" void kernel_launch(void* const* d_in, const int* in_sizes, int n_in,
                              void* d_out, int out_size)
{
    const float* boxes = (const float*)d_in[0];
    const float* p2    = (const float*)d_in[1];
    const float* p3    = (const float*)d_in[2];
    const float* p4    = (const float*)d_in[3];
    const float* p5    = (const float*)d_in[4];
    float4* out = (float4*)d_out;

    pyramid_roi_align_kernel<<<BATCH * NROI, 256>>>(boxes, p2, p3, p4, p5, out);
}